// round 1
// baseline (speedup 1.0000x reference)
#include <cuda_runtime.h>
#include <math.h>

// ---------------------------------------------------------------------------
// Fused CNN: conv1(1->32,3x3,same,relu)+pool2 -> conv2(32->64)+pool2 ->
//            conv3(64->64) -> dense(3136->64,relu) -> dense(64->10)+softmax
// B=2048. All fp32. Packed fma.rn.f32x2 in the hot loops (exact fp32 rounding).
// Intermediates channel-first: P1[b][32][14][14], P2[b][64][7][7].
// ---------------------------------------------------------------------------

#define BATCH 2048

__device__ float g_p1[BATCH * 32 * 14 * 14];   // 51.4 MB
__device__ float g_p2[BATCH * 64 * 7 * 7];     // 25.7 MB

// ---- packed f32x2 helpers (exact fp32 semantics, 2 FMA per instruction) ----
__device__ __forceinline__ unsigned long long pack2(float x) {
    unsigned long long r;
    asm("mov.b64 %0, {%1, %1};" : "=l"(r) : "f"(x));
    return r;
}
__device__ __forceinline__ void ffma2(unsigned long long& d,
                                      unsigned long long a,
                                      unsigned long long b) {
    asm("fma.rn.f32x2 %0, %1, %2, %0;" : "+l"(d) : "l"(a), "l"(b));
}
__device__ __forceinline__ void unpack2(unsigned long long v, float& lo, float& hi) {
    asm("mov.b64 {%0, %1}, %2;" : "=f"(lo), "=f"(hi) : "l"(v));
}

// ---------------------------------------------------------------------------
// K1: conv1 (1->32, 3x3 SAME) + relu + maxpool2  -> P1[b][32][14][14]
// One CTA per image, 256 threads.
// ---------------------------------------------------------------------------
__global__ void __launch_bounds__(256)
k1_conv1(const float* __restrict__ x, const float* __restrict__ w1,
         const float* __restrict__ b1) {
    __shared__ float xs[30 * 30];   // zero-padded input
    __shared__ float w1s[9 * 32];
    __shared__ float b1s[32];

    const int b   = blockIdx.x;
    const int tid = threadIdx.x;

    for (int i = tid; i < 900; i += 256) xs[i] = 0.0f;
    for (int i = tid; i < 288; i += 256) w1s[i] = w1[i];
    if (tid < 32) b1s[tid] = b1[tid];
    __syncthreads();

    const float* xb = x + b * 784;
    for (int i = tid; i < 784; i += 256) {
        int y = i / 28, xx = i % 28;
        xs[(y + 1) * 30 + xx + 1] = xb[i];
    }
    __syncthreads();

    const int oc0  = tid >> 5;   // 0..7
    const int lane = tid & 31;
    float* pb = g_p1 + (size_t)b * 32 * 196;

    for (int oc = oc0; oc < 32; oc += 8) {
        float wk[9];
#pragma unroll
        for (int t = 0; t < 9; t++) wk[t] = w1s[t * 32 + oc];
        const float bias = b1s[oc];

        for (int p = lane; p < 196; p += 32) {
            int py = p / 14, px = p % 14;
            float m = 0.0f;     // relu outputs are >= 0
#pragma unroll
            for (int dy = 0; dy < 2; dy++) {
#pragma unroll
                for (int dx = 0; dx < 2; dx++) {
                    int y = 2 * py + dy, xx = 2 * px + dx;
                    float s = bias;
#pragma unroll
                    for (int ky = 0; ky < 3; ky++)
#pragma unroll
                        for (int kx = 0; kx < 3; kx++)
                            s = fmaf(xs[(y + ky) * 30 + xx + kx], wk[ky * 3 + kx], s);
                    m = fmaxf(m, fmaxf(s, 0.0f));
                }
            }
            pb[oc * 196 + p] = m;
        }
    }
}

// ---------------------------------------------------------------------------
// K2: conv2 (32->64, 3x3 SAME) + relu + maxpool2  -> P2[b][64][7][7]
// One CTA per image, 416 threads (392 compute workers: 8 oc-groups x 49 pools).
// Each worker: 4 conv positions (2x2 pool window) x 8 output channels.
// smem: A[32][16][16] zero-padded acts (32KB) + w2[9][32][64] (72KB).
// ---------------------------------------------------------------------------
__global__ void __launch_bounds__(416, 2)
k2_conv2(const float* __restrict__ w2, const float* __restrict__ b2) {
    extern __shared__ float sm2[];
    float* As  = sm2;           // 8192 floats
    float* w2s = sm2 + 8192;    // 18432 floats
    float* b2s = w2s + 18432;   // 64 floats

    const int b   = blockIdx.x;
    const int tid = threadIdx.x;

    for (int i = tid; i < 8192; i += 416) As[i] = 0.0f;
    for (int i = tid; i < 18432; i += 416) w2s[i] = w2[i];
    if (tid < 64) b2s[tid] = b2[tid];
    __syncthreads();

    const float* pin = g_p1 + (size_t)b * 6272;
    for (int i = tid; i < 6272; i += 416) {
        int ic = i / 196, r = i % 196;
        int y = r / 14, xx = r % 14;
        As[ic * 256 + (y + 1) * 16 + xx + 1] = pin[i];
    }
    __syncthreads();

    if (tid < 392) {
        const int ocg = tid / 49;          // 0..7  -> oc base = ocg*8
        const int p   = tid % 49;
        const int py  = p / 7, px = p % 7;

        unsigned long long acc[4][4];      // [pos(dy*2+dx)][oc-pair]
#pragma unroll
        for (int i = 0; i < 4; i++)
#pragma unroll
            for (int j = 0; j < 4; j++) acc[i][j] = 0ULL;

#pragma unroll
        for (int ky = 0; ky < 3; ky++) {
#pragma unroll
            for (int kx = 0; kx < 3; kx++) {
                const float* ap = As + (2 * py + ky) * 16 + (2 * px + kx);
                const ulonglong2* wp = reinterpret_cast<const ulonglong2*>(
                    w2s + (ky * 3 + kx) * 32 * 64 + ocg * 8);
#pragma unroll 4
                for (int ic = 0; ic < 32; ic++) {
                    unsigned long long a00 = pack2(ap[0]);
                    unsigned long long a01 = pack2(ap[1]);
                    unsigned long long a10 = pack2(ap[16]);
                    unsigned long long a11 = pack2(ap[17]);
                    ulonglong2 w0  = wp[0];
                    ulonglong2 w1v = wp[1];
                    ffma2(acc[0][0], a00, w0.x);  ffma2(acc[0][1], a00, w0.y);
                    ffma2(acc[0][2], a00, w1v.x); ffma2(acc[0][3], a00, w1v.y);
                    ffma2(acc[1][0], a01, w0.x);  ffma2(acc[1][1], a01, w0.y);
                    ffma2(acc[1][2], a01, w1v.x); ffma2(acc[1][3], a01, w1v.y);
                    ffma2(acc[2][0], a10, w0.x);  ffma2(acc[2][1], a10, w0.y);
                    ffma2(acc[2][2], a10, w1v.x); ffma2(acc[2][3], a10, w1v.y);
                    ffma2(acc[3][0], a11, w0.x);  ffma2(acc[3][1], a11, w0.y);
                    ffma2(acc[3][2], a11, w1v.x); ffma2(acc[3][3], a11, w1v.y);
                    ap += 256;
                    wp += 16;   // 64 floats = 16 x 16B
                }
            }
        }

        // bias + relu + 2x2 max-pool, store channel-first
        float* pout = g_p2 + (size_t)b * 64 * 49;
#pragma unroll
        for (int pr = 0; pr < 4; pr++) {
            int oc_lo = ocg * 8 + pr * 2;
            float blo = b2s[oc_lo], bhi = b2s[oc_lo + 1];
            float mlo = 0.0f, mhi = 0.0f;
#pragma unroll
            for (int pos = 0; pos < 4; pos++) {
                float lo, hi;
                unpack2(acc[pos][pr], lo, hi);
                mlo = fmaxf(mlo, fmaxf(lo + blo, 0.0f));
                mhi = fmaxf(mhi, fmaxf(hi + bhi, 0.0f));
            }
            pout[oc_lo * 49 + p]       = mlo;
            pout[(oc_lo + 1) * 49 + p] = mhi;
        }
    }
}

// ---------------------------------------------------------------------------
// K3: conv3 (64->64, 3x3 SAME, relu) + dense1(3136->64, relu)
//     + dense2(64->10) + softmax.  2 images per CTA, 256 threads.
// smem: w3[9][64][64] (144KB) + padded acts 2x[64][9][9] + C3 2x[3136] + misc.
// ---------------------------------------------------------------------------
__global__ void __launch_bounds__(256, 1)
k3_rest(const float* __restrict__ w3, const float* __restrict__ b3,
        const float* __restrict__ wd1, const float* __restrict__ bd1,
        const float* __restrict__ wd2, const float* __restrict__ bd2,
        float* __restrict__ out) {
    extern __shared__ float sm3[];
    float* w3s = sm3;               // 36864
    float* As  = w3s + 36864;       // 2 * 64*81 = 10368 (zero-padded)
    float* Cs  = As + 10368;        // 2 * 3136  = 6272 (NHWC-flattened conv3 out)
    float* b3s = Cs + 6272;         // 64
    float* red = b3s + 64;          // 256
    float* hs  = red + 256;         // 128
    // total 53952 floats = 215808 bytes

    const int tid = threadIdx.x;
    const int b0  = blockIdx.x * 2;

    for (int i = tid; i < 36864; i += 256) w3s[i] = w3[i];
    for (int i = tid; i < 10368; i += 256) As[i] = 0.0f;
    if (tid < 64) b3s[tid] = b3[tid];
    __syncthreads();

#pragma unroll
    for (int img = 0; img < 2; img++) {
        const float* pin = g_p2 + (size_t)(b0 + img) * 3136;
        for (int i = tid; i < 3136; i += 256) {
            int ic = i / 49, r = i % 49;
            int y = r / 7, xx = r % 7;
            As[img * 5184 + ic * 81 + (y + 1) * 9 + xx + 1] = pin[i];
        }
    }
    __syncthreads();

    // ---- conv3: 224 workers = 2 img x 7 rows x 16 oc-groups (4 oc each) ----
    if (tid < 224) {
        const int img = tid / 112;
        const int r   = tid % 112;
        const int row = r >> 4;       // 0..6
        const int ocg = r & 15;       // oc base = ocg*4

        unsigned long long acc[7][2];
#pragma unroll
        for (int i = 0; i < 7; i++) { acc[i][0] = 0ULL; acc[i][1] = 0ULL; }

        const float* Ab = As + img * 5184;
#pragma unroll
        for (int ky = 0; ky < 3; ky++) {
#pragma unroll
            for (int kx = 0; kx < 3; kx++) {
                const float* ap = Ab + (row + ky) * 9 + kx;
                const ulonglong2* wp = reinterpret_cast<const ulonglong2*>(
                    w3s + (ky * 3 + kx) * 64 * 64 + ocg * 4);
#pragma unroll 4
                for (int ic = 0; ic < 64; ic++) {
                    ulonglong2 wv = wp[0];
                    unsigned long long a[7];
#pragma unroll
                    for (int xp = 0; xp < 7; xp++) a[xp] = pack2(ap[xp]);
#pragma unroll
                    for (int xp = 0; xp < 7; xp++) {
                        ffma2(acc[xp][0], a[xp], wv.x);
                        ffma2(acc[xp][1], a[xp], wv.y);
                    }
                    ap += 81;
                    wp += 16;   // 64 floats
                }
            }
        }

        const int oc0 = ocg * 4;
        float bb[4];
#pragma unroll
        for (int j = 0; j < 4; j++) bb[j] = b3s[oc0 + j];
        float* cb = Cs + img * 3136;
#pragma unroll
        for (int xp = 0; xp < 7; xp++) {
            float v0, v1, v2, v3;
            unpack2(acc[xp][0], v0, v1);
            unpack2(acc[xp][1], v2, v3);
            int base = (row * 7 + xp) * 64 + oc0;
            cb[base + 0] = fmaxf(v0 + bb[0], 0.0f);
            cb[base + 1] = fmaxf(v1 + bb[1], 0.0f);
            cb[base + 2] = fmaxf(v2 + bb[2], 0.0f);
            cb[base + 3] = fmaxf(v3 + bb[3], 0.0f);
        }
    }
    __syncthreads();

    // ---- dense1: 3136 -> 64, relu.  2-way K split, 256 workers ----
    {
        const int oc  = tid & 63;
        const int img = (tid >> 6) & 1;
        const int kh  = tid >> 7;
        const float* c   = Cs + img * 3136 + kh * 1568;
        const float* wdp = wd1 + (size_t)(kh * 1568) * 64 + oc;
        float a = 0.0f;
#pragma unroll 4
        for (int k = 0; k < 1568; k++)
            a = fmaf(c[k], __ldg(wdp + (size_t)k * 64), a);
        red[tid] = a;
    }
    __syncthreads();
    if (tid < 128) {
        int oc = tid & 63, img = tid >> 6;
        float v = red[tid] + red[tid + 128] + bd1[oc];
        hs[img * 64 + oc] = fmaxf(v, 0.0f);
    }
    __syncthreads();

    // ---- dense2 + softmax (tiny; 1 thread per image) ----
    if (tid < 2) {
        const int img = tid;
        float lg[10];
#pragma unroll
        for (int c2 = 0; c2 < 10; c2++) {
            float s = bd2[c2];
#pragma unroll
            for (int j = 0; j < 64; j++)
                s = fmaf(hs[img * 64 + j], wd2[j * 10 + c2], s);
            lg[c2] = s;
        }
        float m = lg[0];
#pragma unroll
        for (int c2 = 1; c2 < 10; c2++) m = fmaxf(m, lg[c2]);
        float se = 0.0f;
#pragma unroll
        for (int c2 = 0; c2 < 10; c2++) { lg[c2] = expf(lg[c2] - m); se += lg[c2]; }
        float inv = 1.0f / se;
        float* o = out + (size_t)(b0 + img) * 10;
#pragma unroll
        for (int c2 = 0; c2 < 10; c2++) o[c2] = lg[c2] * inv;
    }
}

// ---------------------------------------------------------------------------
extern "C" void kernel_launch(void* const* d_in, const int* in_sizes, int n_in,
                              void* d_out, int out_size) {
    const float* x   = (const float*)d_in[0];
    const float* w1  = (const float*)d_in[1];
    const float* b1  = (const float*)d_in[2];
    const float* w2  = (const float*)d_in[3];
    const float* b2  = (const float*)d_in[4];
    const float* w3  = (const float*)d_in[5];
    const float* b3  = (const float*)d_in[6];
    const float* wd1 = (const float*)d_in[7];
    const float* bd1 = (const float*)d_in[8];
    const float* wd2 = (const float*)d_in[9];
    const float* bd2 = (const float*)d_in[10];
    float* out = (float*)d_out;

    const int smem2 = (8192 + 18432 + 64) * 4;                      // 106752
    const int smem3 = (36864 + 10368 + 6272 + 64 + 256 + 128) * 4;  // 215808

    cudaFuncSetAttribute(k2_conv2, cudaFuncAttributeMaxDynamicSharedMemorySize, smem2);
    cudaFuncSetAttribute(k3_rest,  cudaFuncAttributeMaxDynamicSharedMemorySize, smem3);

    k1_conv1<<<BATCH, 256>>>(x, w1, b1);
    k2_conv2<<<BATCH, 416, smem2>>>(w2, b2);
    k3_rest<<<BATCH / 2, 256, smem3>>>(w3, b3, wd1, bd1, wd2, bd2, out);
}